// round 4
// baseline (speedup 1.0000x reference)
#include <cuda_runtime.h>
#include <math.h>

#define NNODES 50000
#define NEDGES 1600000
#define F 128
#define LRELU_ALPHA 0.2f

// Scratch (no allocations allowed: __device__ globals)
__device__ float g_hw[NNODES * F];       // h @ W
__device__ float g_ssrc[NNODES];
__device__ float g_sdst[NNODES];
__device__ int   g_rowptr[NNODES + 1];

// ---------------------------------------------------------------------------
// Kernel 1: g_hw = h @ W  (fp32, smem-tiled, BM=64, BK=32, BN=128)
// Fused epilogue: s_src = hw . a_src, s_dst = hw . a_dst via half-warp shfl
// reduction (16 tx-lanes per row group are contiguous lanes).
// ---------------------------------------------------------------------------
__global__ void __launch_bounds__(256) gemm_kernel(const float* __restrict__ h,
                                                   const float* __restrict__ W,
                                                   const float* __restrict__ a_src,
                                                   const float* __restrict__ a_dst) {
    __shared__ float sA[64][32];
    __shared__ float sB[32][128];
    const int tid  = threadIdx.x;
    const int row0 = blockIdx.x * 64;
    const int tx = tid & 15, ty = tid >> 4;
    const int r0 = ty * 4, c0 = tx * 8;

    float acc[4][8];
#pragma unroll
    for (int j = 0; j < 4; j++)
#pragma unroll
        for (int u = 0; u < 8; u++) acc[j][u] = 0.f;

    for (int kt = 0; kt < 4; kt++) {
        // A tile: 64 rows x 32 k (coalesced, guarded)
        for (int i = tid; i < 64 * 32; i += 256) {
            int r = i >> 5, k = i & 31;
            int gr = row0 + r;
            sA[r][k] = (gr < NNODES) ? h[gr * F + kt * 32 + k] : 0.f;
        }
        // B tile: 32 k x 128 cols (float4)
        const float4* W4 = (const float4*)W;
        for (int i = tid; i < 32 * 32; i += 256) {
            int k = i >> 5, c4 = i & 31;
            ((float4*)sB)[k * 32 + c4] = W4[(kt * 32 + k) * 32 + c4];
        }
        __syncthreads();

#pragma unroll
        for (int k = 0; k < 32; k++) {
            float a[4];
#pragma unroll
            for (int j = 0; j < 4; j++) a[j] = sA[r0 + j][k];
            float4 b0 = *(const float4*)&sB[k][c0];
            float4 b1 = *(const float4*)&sB[k][c0 + 4];
#pragma unroll
            for (int j = 0; j < 4; j++) {
                acc[j][0] = fmaf(a[j], b0.x, acc[j][0]);
                acc[j][1] = fmaf(a[j], b0.y, acc[j][1]);
                acc[j][2] = fmaf(a[j], b0.z, acc[j][2]);
                acc[j][3] = fmaf(a[j], b0.w, acc[j][3]);
                acc[j][4] = fmaf(a[j], b1.x, acc[j][4]);
                acc[j][5] = fmaf(a[j], b1.y, acc[j][5]);
                acc[j][6] = fmaf(a[j], b1.z, acc[j][6]);
                acc[j][7] = fmaf(a[j], b1.w, acc[j][7]);
            }
        }
        __syncthreads();
    }

    // ---- epilogue A: store hw tile ----
#pragma unroll
    for (int j = 0; j < 4; j++) {
        int gr = row0 + r0 + j;
        if (gr < NNODES) {
            float4 o0 = make_float4(acc[j][0], acc[j][1], acc[j][2], acc[j][3]);
            float4 o1 = make_float4(acc[j][4], acc[j][5], acc[j][6], acc[j][7]);
            *(float4*)&g_hw[gr * F + c0]     = o0;
            *(float4*)&g_hw[gr * F + c0 + 4] = o1;
        }
    }

    // ---- epilogue B: fused attention scores ----
    float4 as0 = *(const float4*)&a_src[c0];
    float4 as1 = *(const float4*)&a_src[c0 + 4];
    float4 ad0 = *(const float4*)&a_dst[c0];
    float4 ad1 = *(const float4*)&a_dst[c0 + 4];
#pragma unroll
    for (int j = 0; j < 4; j++) {
        float ps = acc[j][0] * as0.x + acc[j][1] * as0.y + acc[j][2] * as0.z + acc[j][3] * as0.w
                 + acc[j][4] * as1.x + acc[j][5] * as1.y + acc[j][6] * as1.z + acc[j][7] * as1.w;
        float pd = acc[j][0] * ad0.x + acc[j][1] * ad0.y + acc[j][2] * ad0.z + acc[j][3] * ad0.w
                 + acc[j][4] * ad1.x + acc[j][5] * ad1.y + acc[j][6] * ad1.z + acc[j][7] * ad1.w;
        // reduce across the 16 tx lanes (contiguous within a half-warp)
#pragma unroll
        for (int o = 8; o; o >>= 1) {
            ps += __shfl_xor_sync(0xffffffffu, ps, o);
            pd += __shfl_xor_sync(0xffffffffu, pd, o);
        }
        int gr = row0 + r0 + j;
        if (tx == 0 && gr < NNODES) {
            g_ssrc[gr] = ps;
            g_sdst[gr] = pd;
        }
    }
}

// ---------------------------------------------------------------------------
// Kernel 2: CSR row pointers from sorted row[] via binary search (no atomics)
// ---------------------------------------------------------------------------
__global__ void rowptr_kernel(const int* __restrict__ row) {
    int n = blockIdx.x * blockDim.x + threadIdx.x;
    if (n > NNODES) return;
    int lo = 0, hi = NEDGES;
    while (lo < hi) {
        int mid = (lo + hi) >> 1;
        if (row[mid] < n) lo = mid + 1; else hi = mid;
    }
    g_rowptr[n] = lo;
}

// ---------------------------------------------------------------------------
// Kernel 3: per-node segment softmax + weighted aggregation + ELU.
// ONE WARP PER NODE (mean degree = 32). 256-thread blocks = 8 nodes/block.
//   Phase 1: chunked lane-per-edge leaky-relu scores, warp shfl max.
//   Phase 2: per 32-edge chunk, lane-per-edge (col, w) in registers; inner
//            loop broadcasts (w_j, col_j) via shfl, every lane gathers its
//            float4 of hw[col_j] (512B coalesced per warp) and accumulates.
//   No shared memory, no block syncs, direct float4 output write.
// ---------------------------------------------------------------------------
__global__ void __launch_bounds__(256) gat_kernel(const int* __restrict__ col,
                                                  float* __restrict__ out) {
    const int n = blockIdx.x * 8 + (threadIdx.x >> 5);
    if (n >= NNODES) return;
    const int lane = threadIdx.x & 31;

    const int start = g_rowptr[n];
    const int end   = g_rowptr[n + 1];
    float4* out4 = (float4*)out;
    if (start == end) {            // empty segment -> elu(0) = 0
        out4[n * 32 + lane] = make_float4(0.f, 0.f, 0.f, 0.f);
        return;
    }
    const float ssrc = g_ssrc[n];

    // ---- phase 1: segment max (lane-per-edge, chunked) ----
    float m = -INFINITY;
    for (int base = start; base < end; base += 32) {
        int i = base + lane;
        if (i < end) {
            float e = ssrc + g_sdst[col[i]];
            e = (e > 0.f) ? e : LRELU_ALPHA * e;
            m = fmaxf(m, e);
        }
    }
#pragma unroll
    for (int o = 16; o; o >>= 1) m = fmaxf(m, __shfl_xor_sync(0xffffffffu, m, o));

    // ---- phase 2: exp weights + feature gather-accumulate ----
    float4 acc = make_float4(0.f, 0.f, 0.f, 0.f);
    float dsum = 0.f;
    const float4* hw4 = (const float4*)g_hw;

    for (int base = start; base < end; base += 32) {
        int i = base + lane;
        int clen = min(32, end - base);
        int c = 0;
        float w = 0.f;
        if (i < end) {
            c = col[i];
            float e = ssrc + g_sdst[c];
            e = (e > 0.f) ? e : LRELU_ALPHA * e;
            w = __expf(e - m);
        }
        dsum += w;
        // broadcast each edge's (w, col) to the whole warp; each lane owns
        // 4 contiguous features -> one 512B coalesced gather per edge
#pragma unroll 4
        for (int j = 0; j < clen; j++) {
            float wj = __shfl_sync(0xffffffffu, w, j);
            int   cj = __shfl_sync(0xffffffffu, c, j);
            float4 v = hw4[cj * 32 + lane];
            acc.x = fmaf(wj, v.x, acc.x);
            acc.y = fmaf(wj, v.y, acc.y);
            acc.z = fmaf(wj, v.z, acc.z);
            acc.w = fmaf(wj, v.w, acc.w);
        }
    }
#pragma unroll
    for (int o = 16; o; o >>= 1) dsum += __shfl_xor_sync(0xffffffffu, dsum, o);

    float inv = 1.f / dsum;
    float4 hp = make_float4(acc.x * inv, acc.y * inv, acc.z * inv, acc.w * inv);
    hp.x = (hp.x > 0.f) ? hp.x : expm1f(hp.x);
    hp.y = (hp.y > 0.f) ? hp.y : expm1f(hp.y);
    hp.z = (hp.z > 0.f) ? hp.z : expm1f(hp.z);
    hp.w = (hp.w > 0.f) ? hp.w : expm1f(hp.w);
    out4[n * 32 + lane] = hp;
}

// ---------------------------------------------------------------------------
extern "C" void kernel_launch(void* const* d_in, const int* in_sizes, int n_in,
                              void* d_out, int out_size) {
    const float* h     = (const float*)d_in[0];
    const float* W     = (const float*)d_in[1];
    const float* a_src = (const float*)d_in[2];
    const float* a_dst = (const float*)d_in[3];
    const int*   row   = (const int*)d_in[4];
    const int*   col   = (const int*)d_in[5];
    float* out = (float*)d_out;

    rowptr_kernel<<<(NNODES + 1 + 255) / 256, 256>>>(row);   // independent of GEMM
    gemm_kernel<<<(NNODES + 63) / 64, 256>>>(h, W, a_src, a_dst);
    gat_kernel<<<(NNODES + 7) / 8, 256>>>(col, out);
}

// round 6
// speedup vs baseline: 1.1117x; 1.1117x over previous
#include <cuda_runtime.h>
#include <cuda_fp16.h>
#include <math.h>

#define NNODES 50000
#define NEDGES 1600000
#define F 128
#define LRELU_ALPHA 0.2f

// Scratch (no allocations allowed: __device__ globals)
__device__ __half g_hwh[NNODES * F];     // h @ W, fp16 (gather table)
__device__ float  g_ssrc[NNODES];
__device__ float  g_sdst[NNODES];
__device__ int    g_rowptr[NNODES + 1];

// ---------------------------------------------------------------------------
// Kernel 1: hw = h @ W  (fp32 compute, smem-tiled, BM=64, BK=32, BN=128)
// Epilogue: store hw as fp16 gather table + fused attention scores
// s_src = hw.a_src, s_dst = hw.a_dst from exact fp32 registers.
// ---------------------------------------------------------------------------
__global__ void __launch_bounds__(256) gemm_kernel(const float* __restrict__ h,
                                                   const float* __restrict__ W,
                                                   const float* __restrict__ a_src,
                                                   const float* __restrict__ a_dst) {
    __shared__ float sA[64][32];
    __shared__ float sB[32][128];
    const int tid  = threadIdx.x;
    const int row0 = blockIdx.x * 64;
    const int tx = tid & 15, ty = tid >> 4;
    const int r0 = ty * 4, c0 = tx * 8;

    float acc[4][8];
#pragma unroll
    for (int j = 0; j < 4; j++)
#pragma unroll
        for (int u = 0; u < 8; u++) acc[j][u] = 0.f;

    for (int kt = 0; kt < 4; kt++) {
        // A tile: 64 rows x 32 k (coalesced, guarded)
        for (int i = tid; i < 64 * 32; i += 256) {
            int r = i >> 5, k = i & 31;
            int gr = row0 + r;
            sA[r][k] = (gr < NNODES) ? h[gr * F + kt * 32 + k] : 0.f;
        }
        // B tile: 32 k x 128 cols (float4)
        const float4* W4 = (const float4*)W;
        for (int i = tid; i < 32 * 32; i += 256) {
            int k = i >> 5, c4 = i & 31;
            ((float4*)sB)[k * 32 + c4] = W4[(kt * 32 + k) * 32 + c4];
        }
        __syncthreads();

#pragma unroll
        for (int k = 0; k < 32; k++) {
            float a[4];
#pragma unroll
            for (int j = 0; j < 4; j++) a[j] = sA[r0 + j][k];
            float4 b0 = *(const float4*)&sB[k][c0];
            float4 b1 = *(const float4*)&sB[k][c0 + 4];
#pragma unroll
            for (int j = 0; j < 4; j++) {
                acc[j][0] = fmaf(a[j], b0.x, acc[j][0]);
                acc[j][1] = fmaf(a[j], b0.y, acc[j][1]);
                acc[j][2] = fmaf(a[j], b0.z, acc[j][2]);
                acc[j][3] = fmaf(a[j], b0.w, acc[j][3]);
                acc[j][4] = fmaf(a[j], b1.x, acc[j][4]);
                acc[j][5] = fmaf(a[j], b1.y, acc[j][5]);
                acc[j][6] = fmaf(a[j], b1.z, acc[j][6]);
                acc[j][7] = fmaf(a[j], b1.w, acc[j][7]);
            }
        }
        __syncthreads();
    }

    // ---- epilogue A: store hw tile as fp16 (8 halves = 16B per row chunk) ----
#pragma unroll
    for (int j = 0; j < 4; j++) {
        int gr = row0 + r0 + j;
        if (gr < NNODES) {
            __half2 q[4];
            q[0] = __floats2half2_rn(acc[j][0], acc[j][1]);
            q[1] = __floats2half2_rn(acc[j][2], acc[j][3]);
            q[2] = __floats2half2_rn(acc[j][4], acc[j][5]);
            q[3] = __floats2half2_rn(acc[j][6], acc[j][7]);
            *(uint4*)&g_hwh[gr * F + c0] = *(uint4*)q;
        }
    }

    // ---- epilogue B: fused attention scores (exact fp32) ----
    float4 as0 = *(const float4*)&a_src[c0];
    float4 as1 = *(const float4*)&a_src[c0 + 4];
    float4 ad0 = *(const float4*)&a_dst[c0];
    float4 ad1 = *(const float4*)&a_dst[c0 + 4];
#pragma unroll
    for (int j = 0; j < 4; j++) {
        float ps = acc[j][0] * as0.x + acc[j][1] * as0.y + acc[j][2] * as0.z + acc[j][3] * as0.w
                 + acc[j][4] * as1.x + acc[j][5] * as1.y + acc[j][6] * as1.z + acc[j][7] * as1.w;
        float pd = acc[j][0] * ad0.x + acc[j][1] * ad0.y + acc[j][2] * ad0.z + acc[j][3] * ad0.w
                 + acc[j][4] * ad1.x + acc[j][5] * ad1.y + acc[j][6] * ad1.z + acc[j][7] * ad1.w;
        // reduce across the 16 tx lanes (contiguous within a half-warp)
#pragma unroll
        for (int o = 8; o; o >>= 1) {
            ps += __shfl_xor_sync(0xffffffffu, ps, o);
            pd += __shfl_xor_sync(0xffffffffu, pd, o);
        }
        int gr = row0 + r0 + j;
        if (tx == 0 && gr < NNODES) {
            g_ssrc[gr] = ps;
            g_sdst[gr] = pd;
        }
    }
}

// ---------------------------------------------------------------------------
// Kernel 2: CSR row pointers by edge-boundary scatter (row[] is sorted).
// rowptr[n] = first edge index with row >= n. Thread i writes all entries in
// (row[i], row[i+1]]; thread 0 also covers [0, row[0]]. Coalesced streaming
// reads, no dependent-load chains, no atomics. Fast path: ~97% of threads
// see r == rn and write nothing.
// ---------------------------------------------------------------------------
__global__ void __launch_bounds__(256) rowptr_kernel(const int* __restrict__ row) {
    int i = blockIdx.x * blockDim.x + threadIdx.x;
    if (i >= NEDGES) return;
    int r  = row[i];
    int rn = (i + 1 < NEDGES) ? row[i + 1] : NNODES;
    if (i == 0) {
        for (int n = 0; n <= r; n++) g_rowptr[n] = 0;
    }
    if (r != rn) {
        for (int n = r + 1; n <= rn; n++) g_rowptr[n] = i + 1;
    }
}

// ---------------------------------------------------------------------------
// Kernel 3: per-node segment softmax + weighted aggregation + ELU.
// ONE WARP PER NODE (mean degree = 32). 256-thread blocks = 8 nodes/block.
//   Phase 1: chunked lane-per-edge leaky-relu scores, warp shfl max.
//   Phase 2: lane-per-edge (col, w) in registers; inner loop broadcasts
//            (w_j, col_j) via shfl, every lane gathers its 4 features as fp16
//            (256B coalesced per warp) and accumulates in fp32.
//   No shared memory, no block syncs, direct float4 output write.
// ---------------------------------------------------------------------------
__global__ void __launch_bounds__(256) gat_kernel(const int* __restrict__ col,
                                                  float* __restrict__ out) {
    const int n = blockIdx.x * 8 + (threadIdx.x >> 5);
    if (n >= NNODES) return;
    const int lane = threadIdx.x & 31;

    const int start = g_rowptr[n];
    const int end   = g_rowptr[n + 1];
    float4* out4 = (float4*)out;
    if (start == end) {            // empty segment -> elu(0) = 0
        out4[n * 32 + lane] = make_float4(0.f, 0.f, 0.f, 0.f);
        return;
    }
    const float ssrc = g_ssrc[n];

    // ---- phase 1: segment max (lane-per-edge, chunked) ----
    float m = -INFINITY;
    for (int base = start; base < end; base += 32) {
        int i = base + lane;
        if (i < end) {
            float e = ssrc + g_sdst[col[i]];
            e = (e > 0.f) ? e : LRELU_ALPHA * e;
            m = fmaxf(m, e);
        }
    }
#pragma unroll
    for (int o = 16; o; o >>= 1) m = fmaxf(m, __shfl_xor_sync(0xffffffffu, m, o));

    // ---- phase 2: exp weights + fp16 feature gather-accumulate ----
    float4 acc = make_float4(0.f, 0.f, 0.f, 0.f);
    float dsum = 0.f;
    const uint2* hwh2 = (const uint2*)g_hwh;   // 4 halves per uint2

    for (int base = start; base < end; base += 32) {
        int i = base + lane;
        int clen = min(32, end - base);
        int c = 0;
        float w = 0.f;
        if (i < end) {
            c = col[i];
            float e = ssrc + g_sdst[c];
            e = (e > 0.f) ? e : LRELU_ALPHA * e;
            w = __expf(e - m);
        }
        dsum += w;
        // broadcast each edge's (w, col); each lane owns 4 contiguous
        // features -> one 256B coalesced fp16 gather per edge
#pragma unroll 4
        for (int j = 0; j < clen; j++) {
            float wj = __shfl_sync(0xffffffffu, w, j);
            int   cj = __shfl_sync(0xffffffffu, c, j);
            uint2 u = hwh2[cj * 32 + lane];
            float2 f0 = __half22float2(*(__half2*)&u.x);
            float2 f1 = __half22float2(*(__half2*)&u.y);
            acc.x = fmaf(wj, f0.x, acc.x);
            acc.y = fmaf(wj, f0.y, acc.y);
            acc.z = fmaf(wj, f1.x, acc.z);
            acc.w = fmaf(wj, f1.y, acc.w);
        }
    }
#pragma unroll
    for (int o = 16; o; o >>= 1) dsum += __shfl_xor_sync(0xffffffffu, dsum, o);

    float inv = 1.f / dsum;
    float4 hp = make_float4(acc.x * inv, acc.y * inv, acc.z * inv, acc.w * inv);
    hp.x = (hp.x > 0.f) ? hp.x : expm1f(hp.x);
    hp.y = (hp.y > 0.f) ? hp.y : expm1f(hp.y);
    hp.z = (hp.z > 0.f) ? hp.z : expm1f(hp.z);
    hp.w = (hp.w > 0.f) ? hp.w : expm1f(hp.w);
    out4[n * 32 + lane] = hp;
}

// ---------------------------------------------------------------------------
extern "C" void kernel_launch(void* const* d_in, const int* in_sizes, int n_in,
                              void* d_out, int out_size) {
    const float* h     = (const float*)d_in[0];
    const float* W     = (const float*)d_in[1];
    const float* a_src = (const float*)d_in[2];
    const float* a_dst = (const float*)d_in[3];
    const int*   row   = (const int*)d_in[4];
    const int*   col   = (const int*)d_in[5];
    float* out = (float*)d_out;

    rowptr_kernel<<<(NEDGES + 255) / 256, 256>>>(row);       // independent of GEMM
    gemm_kernel<<<(NNODES + 63) / 64, 256>>>(h, W, a_src, a_dst);
    gat_kernel<<<(NNODES + 7) / 8, 256>>>(col, out);
}